// round 13
// baseline (speedup 1.0000x reference)
#include <cuda_runtime.h>
#include <cuda_fp16.h>
#include <math.h>
#include <stdint.h>

#define EE 64
#define SSZ 128
#define FF 640
#define HH 256
#define GG 768          // 3*H
#define LLN 20
#define CC 32
#define BB (EE*SSZ)     // 8192
#define BLM (BB*LLN)    // 163840
#define EPSV 1e-5f

// ---------------- scratch (static __device__, no allocation) ----------------
__device__ __half g_xh [BB*FF];
__device__ __half g_x16[BB*HH];
__device__ __half g_gi16[BB*GG];
__device__ __half g_ha16[BB*HH];    // h ping
__device__ __half g_hb16[BB*HH];    // h pong
__device__ __half g_hs16[BLM*HH];   // BN2+PReLU applied
__device__ __half g_y216[BLM*HH];
__device__ __half g_wlin16[HH*FF];
__device__ __half g_wih16[GG*HH];
__device__ __half g_whh16[GG*HH];
__device__ __half g_wc16[HH*HH];
__device__ __half g_wmu16[CC*HH];
__device__ float g_s1[HH], g_o1[HH];
__device__ float g_s2[HH], g_o2[HH];
__device__ float g_s3[HH], g_o3[HH];
__device__ float g_al[3];

// ---------------- helpers ----------------------------------------------------
__device__ __forceinline__ uint32_t cvta_s(const void* p) {
    return (uint32_t)__cvta_generic_to_shared(p);
}
__device__ __forceinline__ void mma16(float* c, const uint32_t* a, const uint32_t* b) {
    asm volatile("mma.sync.aligned.m16n8k16.row.col.f32.f16.f16.f32 "
        "{%0,%1,%2,%3},{%4,%5,%6,%7},{%8,%9},{%0,%1,%2,%3};"
        : "+f"(c[0]), "+f"(c[1]), "+f"(c[2]), "+f"(c[3])
        : "r"(a[0]), "r"(a[1]), "r"(a[2]), "r"(a[3]), "r"(b[0]), "r"(b[1]));
}
#define LDSM4(r0,r1,r2,r3,addr) \
    asm volatile("ldmatrix.sync.aligned.m8n8.x4.shared.b16 {%0,%1,%2,%3}, [%4];" \
        : "=r"(r0),"=r"(r1),"=r"(r2),"=r"(r3) : "r"(addr))

__device__ __forceinline__ float sigf(float x) { return 1.f / (1.f + expf(-x)); }
__device__ __forceinline__ float2 h2f(uint32_t u) { return __half22float2(*(__half2*)&u); }
__device__ __forceinline__ uint32_t f2h(float a, float b) {
    __half2 h = __floats2half2_rn(a, b); return *(uint32_t*)&h;
}

// ---------------- prep ------------------------------------------------------
__global__ void prep_kernel(const float* g1,const float* b1,const float* m1,const float* v1,const float* a1,
                            const float* g2,const float* b2,const float* m2,const float* v2,const float* a2,
                            const float* g3,const float* b3,const float* m3,const float* v3,const float* a3)
{
    int i = threadIdx.x;
    float s;
    s = g1[i] / sqrtf(v1[i] + EPSV); g_s1[i] = s; g_o1[i] = b1[i] - m1[i]*s;
    s = g2[i] / sqrtf(v2[i] + EPSV); g_s2[i] = s; g_o2[i] = b2[i] - m2[i]*s;
    s = g3[i] / sqrtf(v3[i] + EPSV); g_s3[i] = s; g_o3[i] = b3[i] - m3[i]*s;
    if (i == 0) { g_al[0] = a1[0]; g_al[1] = a2[0]; g_al[2] = a3[0]; }
}

__global__ void cvt_kernel(const float* __restrict__ s, __half* __restrict__ d, int n8)
{
    int i = blockIdx.x * blockDim.x + threadIdx.x;
    if (i >= n8) return;
    float4 v0 = *(const float4*)(s + i*8);
    float4 v1 = *(const float4*)(s + i*8 + 4);
    *(uint4*)(d + i*8) = make_uint4(f2h(v0.x,v0.y), f2h(v0.z,v0.w), f2h(v1.x,v1.y), f2h(v1.z,v1.w));
}

// all 5 weight arrays in one launch (keeps ncu's skip-5 on a GEMM)
#define CW0 (HH*FF/8)            // 20480
#define CW1 (CW0 + GG*HH/8)      // 45056
#define CW2 (CW1 + GG*HH/8)      // 69632
#define CW3 (CW2 + HH*HH/8)      // 77824
#define CW4 (CW3 + CC*HH/8)      // 78848
__global__ void cvt_w_kernel(const float* wlin, const float* wih, const float* whh,
                             const float* wc, const float* wmu)
{
    int i = blockIdx.x * blockDim.x + threadIdx.x;
    if (i >= CW4) return;
    const float* s; __half* d; int j;
    if (i < CW0)      { s = wlin; d = g_wlin16; j = i; }
    else if (i < CW1) { s = wih;  d = g_wih16;  j = i - CW0; }
    else if (i < CW2) { s = whh;  d = g_whh16;  j = i - CW1; }
    else if (i < CW3) { s = wc;   d = g_wc16;   j = i - CW2; }
    else              { s = wmu;  d = g_wmu16;  j = i - CW3; }
    float4 v0 = *(const float4*)(s + (size_t)j*8);
    float4 v1 = *(const float4*)(s + (size_t)j*8 + 4);
    *(uint4*)(d + (size_t)j*8) = make_uint4(f2h(v0.x,v0.y), f2h(v0.z,v0.w), f2h(v1.x,v1.y), f2h(v1.z,v1.w));
}

__global__ void zero_h_kernel()
{
    int i = blockIdx.x * blockDim.x + threadIdx.x;   // BB*HH/8
    *(uint4*)(g_ha16 + (size_t)i*8) = make_uint4(0,0,0,0);
}

// ---------------- fp16 GEMM (R12 pipeline, unchanged) ------------------------
template<int BM,int BN,int WM,int WN,int MODE,bool OUTH>
__global__ __launch_bounds__(256, 2) void hgemm3(
    const __half* __restrict__ A, const __half* __restrict__ W,
    const float* __restrict__ bias, void* __restrict__ Cst,
    int M, int N, int K)
{
    constexpr int PIT = 40;
    __shared__ __align__(16) __half Ah[2][BM*PIT];
    __shared__ __align__(16) __half Wh[2][BN*PIT];

    const int tid  = threadIdx.x;
    const int wid  = tid >> 5;
    const int lane = tid & 31;
    const int wm   = wid % WM;
    const int wn   = wid / WM;
    constexpr int WTM = BM / WM;
    constexpr int WTN = BN / WN;
    constexpr int MT  = WTM / 16;
    constexpr int NT  = WTN / 8;
    const int qr = lane >> 2, qc = lane & 3;
    const int l8 = lane & 7;

    const int m0 = blockIdx.y * BM;
    const int n0 = blockIdx.x * BN;

    constexpr int ACH = BM * 4;
    constexpr int WCH = BN * 4;
    constexpr int AIT = ACH / 256;
    constexpr int WIT = (WCH + 255) / 256;

    const int r = tid >> 2, c = tid & 3;

    float acc[MT][NT][4];
#pragma unroll
    for (int i = 0; i < MT; i++)
#pragma unroll
        for (int j = 0; j < NT; j++)
#pragma unroll
            for (int q = 0; q < 4; q++) acc[i][j][q] = 0.f;

    const int T = K / 32;

    {
#pragma unroll
        for (int it = 0; it < AIT; it++) {
            int rr = r + it*64;
            *(uint4*)&Ah[0][rr*PIT + c*8] = *(const uint4*)(A + (size_t)(m0 + rr) * K + c*8);
        }
#pragma unroll
        for (int it = 0; it < WIT; it++) {
            int idx = tid + it*256;
            if ((WCH % 256 == 0) || idx < WCH) {
                int rr = idx >> 2, cc = idx & 3;
                *(uint4*)&Wh[0][rr*PIT + cc*8] = *(const uint4*)(W + (size_t)(n0 + rr) * K + cc*8);
            }
        }
    }
    __syncthreads();

    int buf = 0;
    for (int t = 0; t < T; t++) {
        uint4 aP[AIT], wP[WIT];
        if (t + 1 < T) {
#pragma unroll
            for (int it = 0; it < AIT; it++) {
                int rr = r + it*64;
                aP[it] = *(const uint4*)(A + (size_t)(m0 + rr) * K + (t+1)*32 + c*8);
            }
#pragma unroll
            for (int it = 0; it < WIT; it++) {
                int idx = tid + it*256;
                if ((WCH % 256 == 0) || idx < WCH) {
                    int rr = idx >> 2, cc = idx & 3;
                    wP[it] = *(const uint4*)(W + (size_t)(n0 + rr) * K + (t+1)*32 + cc*8);
                }
            }
        }

#pragma unroll
        for (int ks = 0; ks < 2; ks++) {
            uint32_t af[MT][4], bf[NT][2];
#pragma unroll
            for (int mt = 0; mt < MT; mt++) {
                const int m  = wm*WTM + mt*16 + l8 + ((lane >> 3) & 1) * 8;
                const int ck = 2*ks + (lane >> 4);
                uint32_t ad = cvta_s(&Ah[buf][m*PIT + ck*8]);
                LDSM4(af[mt][0], af[mt][1], af[mt][2], af[mt][3], ad);
            }
#pragma unroll
            for (int np = 0; np < NT/2; np++) {
                const int n  = wn*WTN + np*16 + l8 + ((lane >> 4) & 1) * 8;
                const int ck = 2*ks + ((lane >> 3) & 1);
                uint32_t bd = cvta_s(&Wh[buf][n*PIT + ck*8]);
                LDSM4(bf[2*np][0], bf[2*np][1], bf[2*np+1][0], bf[2*np+1][1], bd);
            }
#pragma unroll
            for (int mt = 0; mt < MT; mt++)
#pragma unroll
                for (int nt = 0; nt < NT; nt++)
                    mma16(acc[mt][nt], af[mt], bf[nt]);
        }

        if (t + 1 < T) {
            const int nb = buf ^ 1;
#pragma unroll
            for (int it = 0; it < AIT; it++) {
                int rr = r + it*64;
                *(uint4*)&Ah[nb][rr*PIT + c*8] = aP[it];
            }
#pragma unroll
            for (int it = 0; it < WIT; it++) {
                int idx = tid + it*256;
                if ((WCH % 256 == 0) || idx < WCH) {
                    int rr = idx >> 2, cc = idx & 3;
                    *(uint4*)&Wh[nb][rr*PIT + cc*8] = wP[it];
                }
            }
            __syncthreads();
            buf = nb;
        }
    }

#pragma unroll
    for (int mt = 0; mt < MT; mt++) {
#pragma unroll
        for (int nt = 0; nt < NT; nt++) {
            const int row = m0 + wm*WTM + mt*16 + qr;
            const int col = n0 + wn*WTN + nt*8 + 2*qc;
            float2 bv = *(const float2*)(bias + col);
            float x0 = acc[mt][nt][0] + bv.x;
            float x1 = acc[mt][nt][1] + bv.y;
            float x2 = acc[mt][nt][2] + bv.x;
            float x3 = acc[mt][nt][3] + bv.y;
            if (MODE == 1 || MODE == 3) {
                const float* sp = (MODE == 1) ? g_s1 : g_s3;
                const float* op = (MODE == 1) ? g_o1 : g_o3;
                const float al  = (MODE == 1) ? g_al[0] : g_al[2];
                float2 sv = *(const float2*)(sp + col);
                float2 ov = *(const float2*)(op + col);
                x0 = fmaf(x0, sv.x, ov.x); x0 = x0>=0.f ? x0 : al*x0;
                x1 = fmaf(x1, sv.y, ov.y); x1 = x1>=0.f ? x1 : al*x1;
                x2 = fmaf(x2, sv.x, ov.x); x2 = x2>=0.f ? x2 : al*x2;
                x3 = fmaf(x3, sv.y, ov.y); x3 = x3>=0.f ? x3 : al*x3;
            }
            if (OUTH) {
                __half* C = (__half*)Cst;
                *(uint32_t*)&C[(size_t)row * N + col]       = f2h(x0, x1);
                *(uint32_t*)&C[(size_t)(row + 8) * N + col] = f2h(x2, x3);
            } else {
                float* C = (float*)Cst;
                *(float2*)&C[(size_t)row * N + col]       = make_float2(x0, x1);
                *(float2*)&C[(size_t)(row + 8) * N + col] = make_float2(x2, x3);
            }
        }
    }
}

// ---------------- fused GRU step ---------------------------------------------
// CTA: 128 batch rows x 64 hidden cols. A (h_in, 128x256 fp16) resident in smem
// for all three gate passes; W slabs streamed double-buffered. r,z kept packed
// fp16 in registers (same fragment coords across passes). n-pass epilogue reads
// h_old from the resident A tile, writes h_out (ping-pong) and hs (BN2+PReLU).
#define PITA 264                      // A row pitch (halfs): 256 + 8
#define PITW 40
#define GRU_SMEM ((128*PITA + 2*64*PITW) * 2)   // 77824 B

__global__ __launch_bounds__(256, 2) void gru_step16(
    const __half* __restrict__ hin, __half* __restrict__ hout,
    const float* __restrict__ bhh, int l)
{
    extern __shared__ __half sm16[];
    __half* Ah = sm16;                       // [128][PITA]
    __half* Wh = sm16 + 128*PITA;            // [2][64][PITW]

    const int tid  = threadIdx.x;
    const int wid  = tid >> 5;
    const int lane = tid & 31;
    const int wm   = wid & 3;                // WM=4 -> WTM=32, MT=2
    const int wn   = wid >> 2;               // WN=2 -> WTN=32, NT=4
    const int qr = lane >> 2, qc = lane & 3;
    const int l8 = lane & 7;

    const int m0 = blockIdx.y * 128;
    const int n0 = blockIdx.x * 64;
    const int wr = tid >> 2, wc = tid & 3;   // W chunk map: 64 rows x 4 chunks

    // ---- load full A (h_in) tile once: 128 x 256 halfs ----
#pragma unroll
    for (int i = 0; i < 16; i++) {
        int idx = tid + i*256;
        int r = idx >> 5, c = idx & 31;
        *(uint4*)&Ah[r*PITA + c*8] = *(const uint4*)(hin + (size_t)(m0 + r) * HH + c*8);
    }

    uint32_t rvp[2][4][2], zvp[2][4][2];

#pragma unroll
    for (int g = 0; g < 3; g++) {
        const __half* Wg = g_whh16 + (size_t)(g*HH + n0) * HH;
        float acc[2][4][4];
#pragma unroll
        for (int i = 0; i < 2; i++)
#pragma unroll
            for (int j = 0; j < 4; j++)
#pragma unroll
                for (int q = 0; q < 4; q++) acc[i][j][q] = 0.f;

        __syncthreads();   // Wh safe to overwrite (and A visible on g=0)
        *(uint4*)&Wh[wr*PITW + wc*8] = *(const uint4*)(Wg + (size_t)wr * HH + wc*8);
        __syncthreads();

        int buf = 0;
        for (int t = 0; t < 8; t++) {        // K=256, BK=32
            uint4 wP;
            if (t < 7)
                wP = *(const uint4*)(Wg + (size_t)wr * HH + (t+1)*32 + wc*8);

#pragma unroll
            for (int ks = 0; ks < 2; ks++) {
                uint32_t af[2][4], bf[4][2];
#pragma unroll
                for (int mt = 0; mt < 2; mt++) {
                    const int m  = wm*32 + mt*16 + l8 + ((lane >> 3) & 1) * 8;
                    const int ck = t*4 + 2*ks + (lane >> 4);
                    uint32_t ad = cvta_s(&Ah[m*PITA + ck*8]);
                    LDSM4(af[mt][0], af[mt][1], af[mt][2], af[mt][3], ad);
                }
#pragma unroll
                for (int np = 0; np < 2; np++) {
                    const int n  = wn*32 + np*16 + l8 + ((lane >> 4) & 1) * 8;
                    const int ck = 2*ks + ((lane >> 3) & 1);
                    uint32_t bd = cvta_s(&Wh[buf*64*PITW + n*PITW + ck*8]);
                    LDSM4(bf[2*np][0], bf[2*np][1], bf[2*np+1][0], bf[2*np+1][1], bd);
                }
#pragma unroll
                for (int mt = 0; mt < 2; mt++)
#pragma unroll
                    for (int nt = 0; nt < 4; nt++)
                        mma16(acc[mt][nt], af[mt], bf[nt]);
            }

            if (t < 7) {
                const int nb = buf ^ 1;
                *(uint4*)&Wh[nb*64*PITW + wr*PITW + wc*8] = wP;
                __syncthreads();
                buf = nb;
            }
        }

        // ---- gate epilogue ----
#pragma unroll
        for (int nt = 0; nt < 4; nt++) {
            const int coll = wn*32 + nt*8 + 2*qc;     // 0..63
            const int colg = n0 + coll;               // 0..255
            float2 bb = *(const float2*)(bhh + g*HH + colg);
#pragma unroll
            for (int mt = 0; mt < 2; mt++) {
#pragma unroll
                for (int hp = 0; hp < 2; hp++) {
                    const int rowl = wm*32 + mt*16 + qr + hp*8;
                    const size_t row = m0 + rowl;
                    const int q = hp*2;
                    float2 gg = h2f(*(const uint32_t*)(g_gi16 + row*GG + g*HH + colg));
                    if (g == 0) {
                        rvp[mt][nt][hp] = f2h(sigf(gg.x + acc[mt][nt][q]   + bb.x),
                                              sigf(gg.y + acc[mt][nt][q+1] + bb.y));
                    } else if (g == 1) {
                        zvp[mt][nt][hp] = f2h(sigf(gg.x + acc[mt][nt][q]   + bb.x),
                                              sigf(gg.y + acc[mt][nt][q+1] + bb.y));
                    } else {
                        float2 rr = h2f(rvp[mt][nt][hp]);
                        float2 zz = h2f(zvp[mt][nt][hp]);
                        float2 ho = h2f(*(const uint32_t*)&Ah[rowl*PITA + colg]);
                        float nn0 = tanhf(gg.x + rr.x*(acc[mt][nt][q]   + bb.x));
                        float nn1 = tanhf(gg.y + rr.y*(acc[mt][nt][q+1] + bb.y));
                        float h0 = (1.f - zz.x)*nn0 + zz.x*ho.x;
                        float h1 = (1.f - zz.y)*nn1 + zz.y*ho.y;
                        *(uint32_t*)(hout + row*HH + colg) = f2h(h0, h1);
                        float2 s2 = *(const float2*)(g_s2 + colg);
                        float2 o2 = *(const float2*)(g_o2 + colg);
                        const float aA = g_al[1];
                        float y0 = fmaf(h0, s2.x, o2.x); y0 = y0>=0.f ? y0 : aA*y0;
                        float y1 = fmaf(h1, s2.y, o2.y); y1 = y1>=0.f ? y1 : aA*y1;
                        *(uint32_t*)(g_hs16 + (row*LLN + l)*HH + colg) = f2h(y0, y1);
                    }
                }
            }
        }
    }
}

// ---------------- launch ----------------------------------------------------
extern "C" void kernel_launch(void* const* d_in, const int* in_sizes, int n_in,
                              void* d_out, int out_size)
{
    const float* A     = (const float*)d_in[0];
    const float* W_lin = (const float*)d_in[1];
    const float* b_lin = (const float*)d_in[2];
    const float* g1    = (const float*)d_in[3];
    const float* be1   = (const float*)d_in[4];
    const float* m1    = (const float*)d_in[5];
    const float* v1    = (const float*)d_in[6];
    const float* a1    = (const float*)d_in[7];
    const float* W_ih  = (const float*)d_in[8];
    const float* W_hh  = (const float*)d_in[9];
    const float* b_ih  = (const float*)d_in[10];
    const float* b_hh  = (const float*)d_in[11];
    const float* g2    = (const float*)d_in[12];
    const float* be2   = (const float*)d_in[13];
    const float* m2    = (const float*)d_in[14];
    const float* v2    = (const float*)d_in[15];
    const float* a2    = (const float*)d_in[16];
    const float* Wc    = (const float*)d_in[17];
    const float* bc    = (const float*)d_in[18];
    const float* g3    = (const float*)d_in[19];
    const float* be3   = (const float*)d_in[20];
    const float* m3    = (const float*)d_in[21];
    const float* v3    = (const float*)d_in[22];
    const float* a3    = (const float*)d_in[23];
    const float* W_mu  = (const float*)d_in[24];
    const float* b_mu  = (const float*)d_in[25];
    float* out = (float*)d_out;

    __half *pxh, *px16, *pgi16, *pha, *phb, *phs16, *py216;
    __half *pwlin, *pwih, *pwc, *pwmu;
    cudaGetSymbolAddress((void**)&pxh,   g_xh);
    cudaGetSymbolAddress((void**)&px16,  g_x16);
    cudaGetSymbolAddress((void**)&pgi16, g_gi16);
    cudaGetSymbolAddress((void**)&pha,   g_ha16);
    cudaGetSymbolAddress((void**)&phb,   g_hb16);
    cudaGetSymbolAddress((void**)&phs16, g_hs16);
    cudaGetSymbolAddress((void**)&py216, g_y216);
    cudaGetSymbolAddress((void**)&pwlin, g_wlin16);
    cudaGetSymbolAddress((void**)&pwih,  g_wih16);
    cudaGetSymbolAddress((void**)&pwc,   g_wc16);
    cudaGetSymbolAddress((void**)&pwmu,  g_wmu16);

    cudaFuncSetAttribute(gru_step16, cudaFuncAttributeMaxDynamicSharedMemorySize, GRU_SMEM);

    prep_kernel<<<1, 256>>>(g1, be1, m1, v1, a1, g2, be2, m2, v2, a2, g3, be3, m3, v3, a3);
    zero_h_kernel<<<(BB*HH/8)/256, 256>>>();

    cvt_kernel<<<(BB*FF/8 + 255)/256, 256>>>(A, pxh, BB*FF/8);
    cvt_w_kernel<<<(CW4 + 255)/256, 256>>>(W_lin, W_ih, W_hh, Wc, W_mu);

    // x = PReLU(BN1(A @ W_lin^T + b_lin)) : [8192,256], K=640
    hgemm3<128,128,4,2,1,true><<<dim3(HH/128, BB/128), 256>>>(pxh, pwlin, b_lin, px16, BB, HH, FF);

    // gi = x @ W_ih^T + b_ih : [8192,768], K=256
    hgemm3<128,128,4,2,0,true><<<dim3(GG/128, BB/128), 256>>>(px16, pwih, b_ih, pgi16, BB, GG, HH);

    // fused GRU: one kernel per step, ping-pong h buffers
    __half* hcur = pha;
    __half* hnxt = phb;
    for (int l = 0; l < LLN; l++) {
        gru_step16<<<dim3(HH/64, BB/128), 256, GRU_SMEM>>>(hcur, hnxt, b_hh, l);
        __half* tmp = hcur; hcur = hnxt; hnxt = tmp;
    }

    // y2 = PReLU(BN3(hs_bn2 @ Wc^T + bc)) : [163840,256], K=256
    hgemm3<128,128,4,2,3,true><<<dim3(HH/128, BLM/128), 256>>>(phs16, pwc, bc, py216, BLM, HH, HH);

    // pred = y2 @ W_mu^T + b_mu : [163840,32] fp32 out
    hgemm3<128,32,4,2,0,false><<<dim3(1, BLM/128), 256>>>(py216, pwmu, b_mu, out, BLM, CC, HH);
}